// round 2
// baseline (speedup 1.0000x reference)
#include <cuda_runtime.h>

#define TT   1024
#define BB   16
#define CC   1024
#define HH   16
#define KW   7
#define PADL 6
#define MM   (TT * BB)       // 16384
#define NN   (HH * KW)       // 112
#define KD   1024

#define BM 64
#define BK 32
#define GEMM_BLOCKS 256
#define ZERO_BLOCKS 2048
#define DENSE_F4    ((size_t)BB * HH * TT * TT / 4)   // 67108864

// softmaxed conv weights, [m = t*16+b][o = h*7+k]
__device__ float g_wsm[(size_t)MM * NN];

typedef unsigned long long ull;
__device__ __forceinline__ ull pk2(float lo, float hi) {
    ull r; asm("mov.b64 %0,{%1,%2};" : "=l"(r) : "f"(lo), "f"(hi)); return r;
}
__device__ __forceinline__ void upk2(ull v, float& lo, float& hi) {
    asm("mov.b64 {%0,%1},%2;" : "=f"(lo), "=f"(hi) : "l"(v));
}
__device__ __forceinline__ void fma2(ull& d, ull a, ull b) {
    asm("fma.rn.f32x2 %0,%1,%2,%3;" : "=l"(d) : "l"(a), "l"(b), "l"(d));
}

// ---------------------------------------------------------------------------
// Kernel 1 (interleaved block roles):
//   blockIdx % 9 == 0  : GEMM w = x@W^T + masked softmax + out epilogue
//   else               : zero-fill slice of dense
// ---------------------------------------------------------------------------
__global__ __launch_bounds__(256)
void k1_fused(const float* __restrict__ x,
              const float* __restrict__ W,
              float* __restrict__ out,
              float* __restrict__ dense)
{
    if (blockIdx.x % 9u != 0u) {
        // ---- zero-fill branch ----
        int zid = blockIdx.x - blockIdx.x / 9u - 1;
        const int per = (int)(DENSE_F4 / ZERO_BLOCKS);            // 32768 f4
        float4* d4 = (float4*)dense + (size_t)zid * per;
        float4 z = make_float4(0.f, 0.f, 0.f, 0.f);
#pragma unroll 4
        for (int i = threadIdx.x; i < per; i += 256)
            __stcs(d4 + i, z);
        return;
    }

    const int gid = blockIdx.x / 9u;

    __shared__ float smem[8192];          // 32 KB, reused (tiles -> sw)
    float* As = smem;                     // [64][33]  As[r*33 + k]
    float* Bs = smem + 64 * 33;           // [112][33] Bs[o*33 + k]

    const int tid   = threadIdx.x;
    const int tx    = tid & 15;           // head
    const int ty    = tid >> 4;           // row micro-group (4 rows)
    const int mBase = gid * BM;

    const int kk  = tid & 31;             // loader column
    const int ldr = tid >> 5;             // loader row phase

    ull acc01[7], acc23[7];
#pragma unroll
    for (int j = 0; j < 7; j++) { acc01[j] = 0ull; acc23[j] = 0ull; }

    for (int k0 = 0; k0 < KD; k0 += BK) {
        // A tile 64x32: coalesced gmem, conflict-free STS (lane stride 1)
#pragma unroll
        for (int rr = 0; rr < 8; rr++) {
            int r = ldr + rr * 8;
            As[r * 33 + kk] = x[(size_t)(mBase + r) * KD + k0 + kk];
        }
        // B tile 112x32
#pragma unroll
        for (int oo = 0; oo < 14; oo++) {
            int o = ldr + oo * 8;
            Bs[o * 33 + kk] = W[(size_t)o * KD + k0 + kk];
        }
        __syncthreads();

#pragma unroll 8
        for (int p = 0; p < BK; p++) {
            float a0 = As[(ty * 4 + 0) * 33 + p];
            float a1 = As[(ty * 4 + 1) * 33 + p];
            float a2 = As[(ty * 4 + 2) * 33 + p];
            float a3 = As[(ty * 4 + 3) * 33 + p];
            ull a01 = pk2(a0, a1);
            ull a23 = pk2(a2, a3);
#pragma unroll
            for (int j = 0; j < 7; j++) {
                float b = Bs[(tx * 7 + j) * 33 + p];   // 7*tx+j mod 32: conflict-free
                ull bb = pk2(b, b);
                fma2(acc01[j], a01, bb);
                fma2(acc23[j], a23, bb);
            }
        }
        __syncthreads();
    }

    // ---- masked softmax over K=7 per (row, head); stash into sw + g_wsm ----
    float accf[4][7];
#pragma unroll
    for (int j = 0; j < 7; j++) {
        upk2(acc01[j], accf[0][j], accf[1][j]);
        upk2(acc23[j], accf[2][j], accf[3][j]);
    }

    float* sw = smem;                     // overlay: sw[r*128 + h*8 + k]
#pragma unroll
    for (int i = 0; i < 4; i++) {
        int r = ty * 4 + i;
        int m = mBase + r;
        int t = m >> 4;
        int kmin = PADL - t; if (kmin < 0) kmin = 0;

        float mx = -1e30f;
#pragma unroll
        for (int k = 0; k < 7; k++)
            if (k >= kmin && accf[i][k] > mx) mx = accf[i][k];

        float e[7], s = 0.f;
#pragma unroll
        for (int k = 0; k < 7; k++) {
            e[k] = (k >= kmin) ? __expf(accf[i][k] - mx) : 0.f;
            s += e[k];
        }
        float inv = 1.f / s;
        float* gp = &g_wsm[(size_t)m * NN + tx * 7];
#pragma unroll
        for (int k = 0; k < 7; k++) {
            float v = e[k] * inv;
            sw[r * 128 + tx * 8 + k] = v;
            gp[k] = v;
        }
    }
    __syncthreads();

    // ---- out epilogue: out[t,b,:] = sum_k sw[t,b,h,k] * x[clamp(t-6+k),b,:] ----
    const int h = tid >> 4;               // float4-chunk tid covers c = 4*tid
    const float4* x4 = (const float4*)x;
    float4* out4 = (float4*)out;
    const int tB = mBase >> 4;

    for (int r = 0; r < 64; r++) {
        int t = tB + (r >> 4);
        int b = r & 15;
        const float* wr = &sw[r * 128 + h * 8];

        float4 acc = make_float4(0.f, 0.f, 0.f, 0.f);
#pragma unroll
        for (int k = 0; k < 7; k++) {
            int pos = t - PADL + k;
            if (pos < 0) pos = 0;         // weight is exactly 0 there
            float wk = wr[k];
            float4 v = x4[((size_t)(pos * BB + b) << 8) + tid];
            acc.x += wk * v.x;
            acc.y += wk * v.y;
            acc.z += wk * v.z;
            acc.w += wk * v.w;
        }
        __stcs(out4 + (((size_t)(t * BB + b)) << 8) + tid, acc);
    }
}

// ---------------------------------------------------------------------------
// Kernel 2: tiny band scatter into the (already zeroed) dense matrix.
// One thread per (t, b, h) writes its 7-float band strip.
// ---------------------------------------------------------------------------
__global__ __launch_bounds__(256)
void k2_band(float* __restrict__ dense)
{
    int gt = blockIdx.x * 256 + threadIdx.x;   // 0 .. 262143
    int t = gt >> 8;
    int b = (gt >> 4) & 15;
    int h = gt & 15;

    const float* wp = &g_wsm[(size_t)(t * BB + b) * NN + h * 7];
    float* dp = &dense[((size_t)(b * HH + h) << 20) + ((size_t)t << 10) + (t - PADL)];
#pragma unroll
    for (int k = 0; k < 7; k++)
        if (t - PADL + k >= 0) dp[k] = wp[k];
}

// ---------------------------------------------------------------------------
extern "C" void kernel_launch(void* const* d_in, const int* in_sizes, int n_in,
                              void* d_out, int out_size)
{
    const float* x = (const float*)d_in[0];   // (T, B, C) fp32
    const float* W = (const float*)d_in[1];   // (H*K, C)  fp32
    float* out   = (float*)d_out;             // first T*B*C floats
    float* dense = out + (size_t)MM * CC;     // then (B*H, T, T)

    k1_fused<<<GEMM_BLOCKS + ZERO_BLOCKS, 256>>>(x, W, out, dense);
    k2_band<<<(MM * HH) / 256, 256>>>(dense);
}

// round 3
// speedup vs baseline: 1.2629x; 1.2629x over previous
#include <cuda_runtime.h>

#define TT   1024
#define BB   16
#define CC   1024
#define HH   16
#define KW   7
#define PADL 6
#define MM   (TT * BB)       // 16384
#define NN   (HH * KW)       // 112
#define KD   1024

#define BM 64
#define BK 32
#define GEMM_BLOCKS 256
#define ZERO_BLOCKS 2048
#define DENSE_F4    ((size_t)BB * HH * TT * TT / 4)   // 67108864

// softmaxed conv weights, [m = t*16+b][o = h*7+k]
__device__ float g_wsm[(size_t)MM * NN];

typedef unsigned long long ull;
__device__ __forceinline__ ull pk2(float lo, float hi) {
    ull r; asm("mov.b64 %0,{%1,%2};" : "=l"(r) : "f"(lo), "f"(hi)); return r;
}
__device__ __forceinline__ void upk2(ull v, float& lo, float& hi) {
    asm("mov.b64 {%0,%1},%2;" : "=f"(lo), "=f"(hi) : "l"(v));
}
__device__ __forceinline__ void fma2(ull& d, ull a, ull b) {
    asm("fma.rn.f32x2 %0,%1,%2,%3;" : "=l"(d) : "l"(a), "l"(b), "l"(d));
}

// ---------------------------------------------------------------------------
// Kernel 1 (interleaved block roles):
//   blockIdx % 9 == 0 : GEMM w = x@W^T + masked softmax  -> g_wsm
//   else              : zero-fill slice of dense
// ---------------------------------------------------------------------------
__global__ __launch_bounds__(256)
void k1_gemm_zero(const float* __restrict__ x,
                  const float* __restrict__ W,
                  float* __restrict__ dense)
{
    if (blockIdx.x % 9u != 0u) {
        // ---- zero-fill branch ----
        int zid = blockIdx.x - blockIdx.x / 9u - 1;
        const int per = (int)(DENSE_F4 / ZERO_BLOCKS);            // 32768 f4
        float4* d4 = (float4*)dense + (size_t)zid * per;
        float4 z = make_float4(0.f, 0.f, 0.f, 0.f);
#pragma unroll 4
        for (int i = threadIdx.x; i < per; i += 256)
            d4[i] = z;
        return;
    }

    const int gid = blockIdx.x / 9u;

    // Row-major tiles, stride 36 floats (16B-aligned rows, conflict-free STS)
    __shared__ __align__(16) float As[BM * 36];    //  64 x 32 (+pad)
    __shared__ __align__(16) float Bs[NN * 36];    // 112 x 32 (+pad)

    const int tid   = threadIdx.x;
    const int tx    = tid & 15;    // head
    const int ty    = tid >> 4;    // row micro-group (4 rows)
    const int row0  = ty * 4;
    const int mBase = gid * BM;

    const int kk  = tid & 31;      // loader column
    const int ldr = tid >> 5;      // loader row phase

    ull acc01[7], acc23[7];
#pragma unroll
    for (int j = 0; j < 7; j++) { acc01[j] = 0ull; acc23[j] = 0ull; }

    for (int k0 = 0; k0 < KD; k0 += BK) {
        // A tile 64x32: gmem coalesced, STS lane-stride 1
#pragma unroll
        for (int rr = 0; rr < 8; rr++) {
            int r = ldr + rr * 8;
            As[r * 36 + kk] = x[(size_t)(mBase + r) * KD + k0 + kk];
        }
        // B tile 112x32 (W is 448 KB -> L2-resident)
#pragma unroll
        for (int oo = 0; oo < 14; oo++) {
            int o = ldr + oo * 8;
            Bs[o * 36 + kk] = W[(size_t)o * KD + k0 + kk];
        }
        __syncthreads();

#pragma unroll
        for (int p0 = 0; p0 < BK; p0 += 4) {
            // 4 rows x 4 p-values of A, via 4 broadcast LDS128
            float4 ar0 = *(const float4*)&As[(row0 + 0) * 36 + p0];
            float4 ar1 = *(const float4*)&As[(row0 + 1) * 36 + p0];
            float4 ar2 = *(const float4*)&As[(row0 + 2) * 36 + p0];
            float4 ar3 = *(const float4*)&As[(row0 + 3) * 36 + p0];

            ull a01[4], a23[4];
            a01[0] = pk2(ar0.x, ar1.x);  a23[0] = pk2(ar2.x, ar3.x);
            a01[1] = pk2(ar0.y, ar1.y);  a23[1] = pk2(ar2.y, ar3.y);
            a01[2] = pk2(ar0.z, ar1.z);  a23[2] = pk2(ar2.z, ar3.z);
            a01[3] = pk2(ar0.w, ar1.w);  a23[3] = pk2(ar2.w, ar3.w);

#pragma unroll
            for (int j = 0; j < 7; j++) {
                float4 b4 = *(const float4*)&Bs[(tx * 7 + j) * 36 + p0];
                ull bb;
                bb = pk2(b4.x, b4.x); fma2(acc01[j], a01[0], bb); fma2(acc23[j], a23[0], bb);
                bb = pk2(b4.y, b4.y); fma2(acc01[j], a01[1], bb); fma2(acc23[j], a23[1], bb);
                bb = pk2(b4.z, b4.z); fma2(acc01[j], a01[2], bb); fma2(acc23[j], a23[2], bb);
                bb = pk2(b4.w, b4.w); fma2(acc01[j], a01[3], bb); fma2(acc23[j], a23[3], bb);
            }
        }
        __syncthreads();
    }

    // ---- masked softmax over K=7 per (row, head) -> g_wsm ----
    float accf[4][7];
#pragma unroll
    for (int j = 0; j < 7; j++) {
        upk2(acc01[j], accf[0][j], accf[1][j]);
        upk2(acc23[j], accf[2][j], accf[3][j]);
    }

#pragma unroll
    for (int i = 0; i < 4; i++) {
        int m = mBase + row0 + i;
        int t = m >> 4;
        int kmin = PADL - t; if (kmin < 0) kmin = 0;

        float mx = -1e30f;
#pragma unroll
        for (int k = 0; k < 7; k++)
            if (k >= kmin && accf[i][k] > mx) mx = accf[i][k];

        float e[7], s = 0.f;
#pragma unroll
        for (int k = 0; k < 7; k++) {
            e[k] = (k >= kmin) ? __expf(accf[i][k] - mx) : 0.f;
            s += e[k];
        }
        float inv = 1.f / s;
        float* gp = &g_wsm[(size_t)m * NN + tx * 7];
#pragma unroll
        for (int k = 0; k < 7; k++)
            gp[k] = e[k] * inv;
    }
}

// ---------------------------------------------------------------------------
// Kernel 2 (R1 version, measured 41.9us):
//   out[t,b,:] = sum_k wsm[t,b,h,k] * x[clamp(t-6+k), b, :]
//   + scatter the 7-wide band of wsm into dense (zeros already laid)
// One block per (t, b); 256 threads, one float4 of C each.
// ---------------------------------------------------------------------------
__global__ __launch_bounds__(256)
void k2_out_band(const float* __restrict__ x,
                 float* __restrict__ out,
                 float* __restrict__ dense)
{
    const int t   = blockIdx.x;
    const int b   = blockIdx.y;
    const int tid = threadIdx.x;

    __shared__ float sw[NN];
    if (tid < NN)
        sw[tid] = g_wsm[(size_t)(t * BB + b) * NN + tid];
    __syncthreads();

    const int h = tid >> 4;                 // c = 4*tid, head = c/64
    const float4* x4 = (const float4*)x;

    float4 acc = make_float4(0.f, 0.f, 0.f, 0.f);
#pragma unroll
    for (int k = 0; k < 7; k++) {
        int pos = t - PADL + k;
        if (pos < 0) pos = 0;               // weight is exactly 0 there
        float wk = sw[h * 7 + k];
        float4 v = x4[((size_t)(pos * BB + b) << 8) + tid];
        acc.x += wk * v.x;
        acc.y += wk * v.y;
        acc.z += wk * v.z;
        acc.w += wk * v.w;
    }
    float4* out4 = (float4*)out;
    out4[((size_t)(t * BB + b) << 8) + tid] = acc;

    // band scatter
    if (tid < NN) {
        int hh  = tid / 7;
        int k   = tid - hh * 7;
        int col = t - PADL + k;
        if (col >= 0) {
            dense[((size_t)(b * HH + hh) << 20) + ((size_t)t << 10) + col] = sw[tid];
        }
    }
}

// ---------------------------------------------------------------------------
extern "C" void kernel_launch(void* const* d_in, const int* in_sizes, int n_in,
                              void* d_out, int out_size)
{
    const float* x = (const float*)d_in[0];   // (T, B, C) fp32
    const float* W = (const float*)d_in[1];   // (H*K, C)  fp32
    float* out   = (float*)d_out;             // first T*B*C floats
    float* dense = out + (size_t)MM * CC;     // then (B*H, T, T)

    k1_gemm_zero<<<GEMM_BLOCKS + ZERO_BLOCKS, 256>>>(x, W, dense);

    dim3 g2(TT, BB);
    k2_out_band<<<g2, 256>>>(x, out, dense);
}

// round 4
// speedup vs baseline: 1.3297x; 1.0529x over previous
#include <cuda_runtime.h>

#define TT   1024
#define BB   16
#define CC   1024
#define HH   16
#define KW   7
#define PADL 6
#define MM   (TT * BB)       // 16384
#define NN   (HH * KW)       // 112
#define KD   1024

#define BM 64
#define BK 32
#define GEMM_BLOCKS (MM / BM)                 // 256
#define DENSE_BYTES ((size_t)BB * HH * TT * TT * 4)   // 1 GiB

// softmaxed conv weights, [m = t*16+b][o = h*7+k]
__device__ float g_wsm[(size_t)MM * NN];

typedef unsigned long long ull;
__device__ __forceinline__ ull pk2(float lo, float hi) {
    ull r; asm("mov.b64 %0,{%1,%2};" : "=l"(r) : "f"(lo), "f"(hi)); return r;
}
__device__ __forceinline__ void upk2(ull v, float& lo, float& hi) {
    asm("mov.b64 {%0,%1},%2;" : "=f"(lo), "=f"(hi) : "l"(v));
}
__device__ __forceinline__ void fma2(ull& d, ull a, ull b) {
    asm("fma.rn.f32x2 %0,%1,%2,%3;" : "=l"(d) : "l"(a), "l"(b), "l"(d));
}

// ---------------------------------------------------------------------------
// GEMM  w = x @ W^T  (16384 x 112 x 1024) + masked softmax over K=7 -> g_wsm
// Shared layouts chosen so the f32x2 operands come straight out of LDS:
//   Asf[p][m], stride 66 floats : LDS64 at (p,4ty) = rows (4ty,4ty+1) packed
//   Bsd[o][p] pre-duplicated (b,b) ull, stride 34 : LDS128 = 2 broadcast pairs
// ---------------------------------------------------------------------------
#define ASTR 66
#define BSTR 34

__global__ __launch_bounds__(256)
void k_gemm_softmax(const float* __restrict__ x,
                    const float* __restrict__ W)
{
    __shared__ __align__(16) float Asf[BK * ASTR];     //  8448 B
    __shared__ __align__(16) ull   Bsd[NN * BSTR];     // 30464 B

    const int tid   = threadIdx.x;
    const int tx    = tid & 15;     // head
    const int ty    = tid >> 4;     // row micro-group (4 rows)
    const int mBase = blockIdx.x * BM;

    const int kk  = tid & 31;       // loader: k within tile
    const int ldr = tid >> 5;       // loader: row phase 0..7

    ull acc01[7], acc23[7];
#pragma unroll
    for (int j = 0; j < 7; j++) { acc01[j] = 0ull; acc23[j] = 0ull; }

    for (int k0 = 0; k0 < KD; k0 += BK) {
        // A tile: gmem coalesced in k, STS to k-major (2-way conflict, amortized)
#pragma unroll
        for (int rr = 0; rr < 8; rr++) {
            int r = ldr + rr * 8;
            Asf[kk * ASTR + r] = x[(size_t)(mBase + r) * KD + k0 + kk];
        }
        // B tile: store value duplicated into both f32x2 lanes
#pragma unroll
        for (int oo = 0; oo < 14; oo++) {
            int o = ldr + oo * 8;
            float w = W[(size_t)o * KD + k0 + kk];
            Bsd[o * BSTR + kk] = pk2(w, w);
        }
        __syncthreads();

#pragma unroll
        for (int p = 0; p < BK; p += 2) {
            ull a01_0 = *(const ull*)&Asf[p * ASTR + 4 * ty];
            ull a23_0 = *(const ull*)&Asf[p * ASTR + 4 * ty + 2];
            ull a01_1 = *(const ull*)&Asf[(p + 1) * ASTR + 4 * ty];
            ull a23_1 = *(const ull*)&Asf[(p + 1) * ASTR + 4 * ty + 2];
#pragma unroll
            for (int j = 0; j < 7; j++) {
                ulonglong2 bb = *(const ulonglong2*)&Bsd[(tx * 7 + j) * BSTR + p];
                fma2(acc01[j], a01_0, bb.x);
                fma2(acc23[j], a23_0, bb.x);
                fma2(acc01[j], a01_1, bb.y);
                fma2(acc23[j], a23_1, bb.y);
            }
        }
        __syncthreads();
    }

    // ---- masked softmax over K=7 per (row, head) -> g_wsm ----
    float accf[4][7];
#pragma unroll
    for (int j = 0; j < 7; j++) {
        upk2(acc01[j], accf[0][j], accf[1][j]);
        upk2(acc23[j], accf[2][j], accf[3][j]);
    }

#pragma unroll
    for (int i = 0; i < 4; i++) {
        int m = mBase + ty * 4 + i;
        int t = m >> 4;
        int kmin = PADL - t; if (kmin < 0) kmin = 0;

        float mx = -1e30f;
#pragma unroll
        for (int k = 0; k < 7; k++)
            if (k >= kmin && accf[i][k] > mx) mx = accf[i][k];

        float e[7], s = 0.f;
#pragma unroll
        for (int k = 0; k < 7; k++) {
            e[k] = (k >= kmin) ? __expf(accf[i][k] - mx) : 0.f;
            s += e[k];
        }
        float inv = 1.f / s;
        float* gp = &g_wsm[(size_t)m * NN + tx * 7];
#pragma unroll
        for (int k = 0; k < 7; k++)
            gp[k] = e[k] * inv;
    }
}

// ---------------------------------------------------------------------------
// k2: two consecutive t per block; rows share 6 of their 7 gather rows.
//   out[t,b,:] = sum_k wsm[t,b,h,k] * x[clamp(t-6+k), b, :]
//   + band scatter into (already zeroed) dense
// ---------------------------------------------------------------------------
__global__ __launch_bounds__(256)
void k2_out_band(const float* __restrict__ x,
                 float* __restrict__ out,
                 float* __restrict__ dense)
{
    const int t0  = blockIdx.x * 2;
    const int b   = blockIdx.y;
    const int tid = threadIdx.x;

    __shared__ float sw[2 * NN];
    if (tid < 2 * NN) {
        int row = tid / NN, idx = tid - row * NN;
        sw[tid] = g_wsm[(size_t)((t0 + row) * BB + b) * NN + idx];
    }
    __syncthreads();

    const int h = tid >> 4;
    const float4* x4 = (const float4*)x;

    float4 v[8];
#pragma unroll
    for (int k = 0; k < 8; k++) {
        int pos = t0 - PADL + k;
        if (pos < 0) pos = 0;               // weight is exactly 0 there
        v[k] = x4[((size_t)(pos * BB + b) << 8) + tid];
    }

    const float* w0 = &sw[h * 7];
    const float* w1 = &sw[NN + h * 7];
    float4 a0 = make_float4(0.f, 0.f, 0.f, 0.f);
    float4 a1 = make_float4(0.f, 0.f, 0.f, 0.f);
#pragma unroll
    for (int k = 0; k < 7; k++) {
        float wk0 = w0[k], wk1 = w1[k];
        a0.x += wk0 * v[k].x;     a1.x += wk1 * v[k + 1].x;
        a0.y += wk0 * v[k].y;     a1.y += wk1 * v[k + 1].y;
        a0.z += wk0 * v[k].z;     a1.z += wk1 * v[k + 1].z;
        a0.w += wk0 * v[k].w;     a1.w += wk1 * v[k + 1].w;
    }
    float4* out4 = (float4*)out;
    out4[((size_t)(t0 * BB + b) << 8) + tid] = a0;
    out4[((size_t)((t0 + 1) * BB + b) << 8) + tid] = a1;

    // band scatter for both rows
    if (tid < 2 * NN) {
        int row = tid / NN, idx = tid - row * NN;
        int hh  = idx / 7;
        int k   = idx - hh * 7;
        int t   = t0 + row;
        int col = t - PADL + k;
        if (col >= 0)
            dense[((size_t)(b * HH + hh) << 20) + ((size_t)t << 10) + col] = sw[tid];
    }
}

// ---------------------------------------------------------------------------
extern "C" void kernel_launch(void* const* d_in, const int* in_sizes, int n_in,
                              void* d_out, int out_size)
{
    const float* x = (const float*)d_in[0];   // (T, B, C) fp32
    const float* W = (const float*)d_in[1];   // (H*K, C)  fp32
    float* out   = (float*)d_out;             // first T*B*C floats
    float* dense = out + (size_t)MM * CC;     // then (B*H, T, T)

    k_gemm_softmax<<<GEMM_BLOCKS, 256>>>(x, W);

    cudaMemsetAsync(dense, 0, DENSE_BYTES);   // graph memset node

    dim3 g2(TT / 2, BB);
    k2_out_band<<<g2, 256>>>(x, out, dense);
}